// round 11
// baseline (speedup 1.0000x reference)
#include <cuda_runtime.h>
#include <cuda_fp16.h>
#include <cstdint>

#define Bn 32768
#define Kn 8192
#define Dn 512
#define DECAYF 0.99f
#define OMDF   0.01f
#define EPSF   1e-5f

#define NITER 8              // K=512, BLK_K=64 (bytes, int8)
#define STB 10240            // per stage: 128 rows * 80B (64B data + 16 pad)
#define SM_CSQ  61440        // after 3*STB*2
#define SM_SCS  61952
#define SM_SZS  62464
#define SMEM_BYTES 62976

// Device scratch (allocation-free). NEVER referenced from host code.
__device__ uint4  g_A4[(size_t)Bn * Dn / 16];         // s8 of z_e
__device__ uint4  g_B4[(size_t)Kn * Dn / 16];         // s8 of codebook
__device__ __half g_scores[(size_t)Bn * Kn];          // approx scores
__device__ float  g_embed[(size_t)Kn * Dn];
__device__ float  g_counts[Kn];
__device__ float  g_csq[Kn];
__device__ float  g_sz[Bn];                           // z row scales
__device__ float  g_sc[Kn];                           // codebook row scales
__device__ unsigned g_scmax_bits;                     // max s_c (float bits)
__device__ unsigned g_l1cmax_bits;                    // max L1(c) (float bits)

__device__ __forceinline__ uint32_t smem_u32(const void* p) {
    uint32_t a;
    asm("{ .reg .u64 t; cvta.to.shared.u64 t, %1; cvt.u32.u64 %0, t; }"
        : "=r"(a) : "l"(p));
    return a;
}
__device__ __forceinline__ void cpa16(uint32_t s, const void* g) {
    asm volatile("cp.async.cg.shared.global [%0], [%1], 16;" :: "r"(s), "l"(g));
}
#define CP_COMMIT() asm volatile("cp.async.commit_group;" ::: "memory")
#define CP_WAIT1()  asm volatile("cp.async.wait_group 1;" ::: "memory")

__device__ __forceinline__ void ldsm4(uint32_t& r0, uint32_t& r1, uint32_t& r2,
                                      uint32_t& r3, uint32_t addr) {
    asm volatile("ldmatrix.sync.aligned.m8n8.x4.shared.b16 {%0,%1,%2,%3}, [%4];"
                 : "=r"(r0), "=r"(r1), "=r"(r2), "=r"(r3) : "r"(addr));
}
__device__ __forceinline__ void imma(int* c, uint32_t a0, uint32_t a1,
                                     uint32_t a2, uint32_t a3,
                                     uint32_t b0, uint32_t b1) {
    asm volatile(
        "mma.sync.aligned.m16n8k32.row.col.s32.s8.s8.s32 "
        "{%0,%1,%2,%3}, {%4,%5,%6,%7}, {%8,%9}, {%0,%1,%2,%3};"
        : "+r"(c[0]), "+r"(c[1]), "+r"(c[2]), "+r"(c[3])
        : "r"(a0), "r"(a1), "r"(a2), "r"(a3), "r"(b0), "r"(b1));
}
__device__ __forceinline__ unsigned f2ord(float f) {
    unsigned u = __float_as_uint(f);
    return (u & 0x80000000u) ? ~u : (u | 0x80000000u);
}
__device__ __forceinline__ uint32_t pack4(int q0, int q1, int q2, int q3) {
    return (q0 & 0xFF) | ((q1 & 0xFF) << 8) | ((q2 & 0xFF) << 16)
         | ((uint32_t)(q3 & 0xFF) << 24);
}

// ---------------------------------------------------------------------------
__global__ void zero_kernel() {
    int stride = gridDim.x * blockDim.x;
    int t = blockIdx.x * blockDim.x + threadIdx.x;
    const int N = Kn * Dn;
    for (int i = t; i < N; i += stride) g_embed[i] = 0.0f;
    if (t < Kn) g_counts[t] = 0.0f;
    if (t == 0) { g_scmax_bits = 0u; g_l1cmax_bits = 0u; }
}

// per-row int8 quantization (round-to-nearest, s = max|row|/127)
__global__ void quantA_kernel(const float* __restrict__ src) {
    int row = (blockIdx.x * blockDim.x + threadIdx.x) >> 5;
    int lane = threadIdx.x & 31;
    if (row >= Bn) return;
    const float4* r = (const float4*)(src + (size_t)row * Dn) + lane * 4;
    float4 v[4];
    float mx = 0.0f;
    #pragma unroll
    for (int i = 0; i < 4; i++) {
        v[i] = r[i];
        mx = fmaxf(mx, fmaxf(fmaxf(fabsf(v[i].x), fabsf(v[i].y)),
                             fmaxf(fabsf(v[i].z), fabsf(v[i].w))));
    }
    #pragma unroll
    for (int o = 16; o > 0; o >>= 1) mx = fmaxf(mx, __shfl_xor_sync(0xFFFFFFFFu, mx, o));
    float s = fmaxf(mx, 1e-10f) / 127.0f;
    float inv = 1.0f / s;
    uint32_t p[4];
    #pragma unroll
    for (int i = 0; i < 4; i++)
        p[i] = pack4(__float2int_rn(v[i].x * inv), __float2int_rn(v[i].y * inv),
                     __float2int_rn(v[i].z * inv), __float2int_rn(v[i].w * inv));
    ((uint4*)((char*)(void*)g_A4 + (size_t)row * Dn))[lane] =
        make_uint4(p[0], p[1], p[2], p[3]);
    if (lane == 0) g_sz[row] = s;
}

// codebook: quantize + exact csq + L1 + global maxes
__global__ void quantB_kernel(const float* __restrict__ src) {
    int row = (blockIdx.x * blockDim.x + threadIdx.x) >> 5;
    int lane = threadIdx.x & 31;
    if (row >= Kn) return;
    const float4* r = (const float4*)(src + (size_t)row * Dn) + lane * 4;
    float4 v[4];
    float mx = 0.0f, sq = 0.0f, l1 = 0.0f;
    #pragma unroll
    for (int i = 0; i < 4; i++) {
        v[i] = r[i];
        mx = fmaxf(mx, fmaxf(fmaxf(fabsf(v[i].x), fabsf(v[i].y)),
                             fmaxf(fabsf(v[i].z), fabsf(v[i].w))));
        sq += v[i].x * v[i].x + v[i].y * v[i].y + v[i].z * v[i].z + v[i].w * v[i].w;
        l1 += fabsf(v[i].x) + fabsf(v[i].y) + fabsf(v[i].z) + fabsf(v[i].w);
    }
    #pragma unroll
    for (int o = 16; o > 0; o >>= 1) {
        mx = fmaxf(mx, __shfl_xor_sync(0xFFFFFFFFu, mx, o));
        sq += __shfl_xor_sync(0xFFFFFFFFu, sq, o);
        l1 += __shfl_xor_sync(0xFFFFFFFFu, l1, o);
    }
    float s = fmaxf(mx, 1e-10f) / 127.0f;
    float inv = 1.0f / s;
    uint32_t p[4];
    #pragma unroll
    for (int i = 0; i < 4; i++)
        p[i] = pack4(__float2int_rn(v[i].x * inv), __float2int_rn(v[i].y * inv),
                     __float2int_rn(v[i].z * inv), __float2int_rn(v[i].w * inv));
    ((uint4*)((char*)(void*)g_B4 + (size_t)row * Dn))[lane] =
        make_uint4(p[0], p[1], p[2], p[3]);
    if (lane == 0) {
        g_csq[row] = sq;
        g_sc[row] = s;
        atomicMax(&g_scmax_bits, __float_as_uint(s));     // s>0: bit order ok
        atomicMax(&g_l1cmax_bits, __float_as_uint(l1));
    }
}

// ---------------------------------------------------------------------------
// Pass 1: s8 IMMA GEMM (m16n8k32), approx scores -> g_scores (fp16, streamed).
// Block 128x128, 4 warps (2x2), warp tile 64x64, BLK_K=64B, 3-slot cp.async.
// ---------------------------------------------------------------------------
__global__ void __launch_bounds__(128, 2)
gemm_kernel() {
    extern __shared__ char sm[];
    const uint32_t sA = smem_u32(sm);
    const uint32_t sB = sA + 3 * STB;
    float* csq_s = (float*)(sm + SM_CSQ);
    float* scs_s = (float*)(sm + SM_SCS);
    float* szs_s = (float*)(sm + SM_SZS);

    const int tid = threadIdx.x;
    const int lane = tid & 31;
    const int w = tid >> 5;
    const int warpM = w & 1;
    const int warpN = w >> 1;
    const int rowBase = (blockIdx.x >> 6) * 128;
    const int colBase = (blockIdx.x & 63) * 128;   // colTile-fastest: B L2-resident

    csq_s[tid] = g_csq[colBase + tid];
    scs_s[tid] = g_sc[colBase + tid];
    szs_s[tid] = g_sz[rowBase + tid];

    const signed char* A = (const signed char*)(void*)g_A4;
    const signed char* Bm = (const signed char*)(void*)g_B4;

    // loader: 512 16B-chunks per matrix per stage; 128 threads -> 4 each
    const int lr = tid >> 2, lc = tid & 3;         // row 0..31, chunk 0..3
    const uint32_t soBase = (uint32_t)(lr * 80 + lc * 16);
    const signed char* gA = A + (size_t)(rowBase + lr) * Dn + lc * 16;
    const signed char* gB = Bm + (size_t)(colBase + lr) * Dn + lc * 16;

    int acc[4][8][4];
    #pragma unroll
    for (int mt = 0; mt < 4; mt++)
        #pragma unroll
        for (int nt = 0; nt < 8; nt++)
            #pragma unroll
            for (int r = 0; r < 4; r++) acc[mt][nt][r] = 0;

    const int lrow = lane & 15;
    const int khalf = lane >> 4;
    const uint32_t aRowOff = (uint32_t)((warpM * 64 + lrow) * 80 + khalf * 16);
    const uint32_t bRowOff = (uint32_t)((warpN * 64 + lrow) * 80 + khalf * 16);

    #define LOAD_STAGE(s, slot) do {                                           \
        int _off = (s) << 6;                                                   \
        uint32_t _da = sA + (slot) * STB;                                      \
        uint32_t _db = sB + (slot) * STB;                                      \
        _Pragma("unroll")                                                      \
        for (int it = 0; it < 4; it++) {                                       \
            uint32_t so = soBase + it * 32 * 80;                               \
            cpa16(_da + so, gA + (size_t)(it * 32) * Dn + _off);               \
            cpa16(_db + so, gB + (size_t)(it * 32) * Dn + _off);               \
        }                                                                      \
    } while (0)

    LOAD_STAGE(0, 0); CP_COMMIT();
    LOAD_STAGE(1, 1); CP_COMMIT();

    int slot = 0, nslot = 2;
    #pragma unroll 1
    for (int s = 0; s < NITER; s++) {
        CP_WAIT1();
        __syncthreads();
        if (s + 2 < NITER) LOAD_STAGE(s + 2, nslot);
        CP_COMMIT();

        const uint32_t da = sA + slot * STB;
        const uint32_t db = sB + slot * STB;
        #pragma unroll
        for (int k32 = 0; k32 < 2; k32++) {
            uint32_t a[4][4];
            #pragma unroll
            for (int mt = 0; mt < 4; mt++)
                ldsm4(a[mt][0], a[mt][1], a[mt][2], a[mt][3],
                      da + aRowOff + mt * 16 * 80 + k32 * 32);
            uint32_t b[4][4];
            #pragma unroll
            for (int np = 0; np < 4; np++)
                ldsm4(b[np][0], b[np][1], b[np][2], b[np][3],
                      db + bRowOff + np * 16 * 80 + k32 * 32);
            #pragma unroll
            for (int mt = 0; mt < 4; mt++)
                #pragma unroll
                for (int nt = 0; nt < 8; nt++)
                    imma(acc[mt][nt],
                         a[mt][0], a[mt][1], a[mt][2], a[mt][3],
                         b[nt >> 1][(nt & 1) ? 1 : 0],
                         b[nt >> 1][(nt & 1) ? 3 : 2]);
        }
        slot = slot == 2 ? 0 : slot + 1;
        nslot = nslot == 2 ? 0 : nslot + 1;
    }
    #undef LOAD_STAGE

    // epilogue: score = csq - 2*s_z*s_c*idot, streamed fp16 writes
    const int g = lane >> 2, tg = lane & 3;
    #pragma unroll
    for (int mt = 0; mt < 4; mt++) {
        #pragma unroll
        for (int half = 0; half < 2; half++) {
            int lrowE = warpM * 64 + mt * 16 + half * 8 + g;
            int grow = rowBase + lrowE;
            float sz2 = 2.0f * szs_s[lrowE];
            unsigned* dst = (unsigned*)(g_scores + (size_t)grow * Kn + colBase);
            #pragma unroll
            for (int nt = 0; nt < 8; nt++) {
                int cl = warpN * 64 + nt * 8 + tg * 2;
                float s0 = fmaf(-sz2 * scs_s[cl],
                                (float)acc[mt][nt][half * 2 + 0], csq_s[cl]);
                float s1 = fmaf(-sz2 * scs_s[cl + 1],
                                (float)acc[mt][nt][half * 2 + 1], csq_s[cl + 1]);
                __half2 h = __floats2half2_rn(s0, s1);
                __stcs(dst + (cl >> 1), *(unsigned*)&h);
            }
        }
    }
}

// ---------------------------------------------------------------------------
// Pass 2 (fused with scatter): scan scores, exact fp32 rescore of candidates,
// write z_q + indices, atomic scatter counts/embed. One 256-thread block/row.
// ---------------------------------------------------------------------------
#define MAXCAND 256
__global__ void __launch_bounds__(256)
select_kernel(const float* __restrict__ z_e, const float* __restrict__ cb,
              float* __restrict__ out) {
    __shared__ float zs[Dn];
    __shared__ float rl[8], rs[8];
    __shared__ int list[MAXCAND];
    __shared__ int cnt;
    __shared__ float thrS;
    __shared__ unsigned long long bestPk;

    const int row = blockIdx.x;
    const int t = threadIdx.x;
    const int lane = t & 31, wid = t >> 5;

    float2 zv = ((const float2*)(z_e + (size_t)row * Dn))[t];
    ((float2*)zs)[t] = zv;
    float zl = fabsf(zv.x) + fabsf(zv.y);
    #pragma unroll
    for (int o = 16; o > 0; o >>= 1) zl += __shfl_xor_sync(0xFFFFFFFFu, zl, o);
    if (lane == 0) rl[wid] = zl;
    if (t == 0) { cnt = 0; bestPk = 0xFFFFFFFFFFFFFFFFull; }

    const uint4* sr = (const uint4*)(g_scores + (size_t)row * Kn);
    uint4 sv[4];
    float mn = 3.4e38f;
    #pragma unroll
    for (int i = 0; i < 4; i++) {
        sv[i] = __ldcs(sr + t + (i << 8));
        const unsigned* u = (const unsigned*)&sv[i];
        #pragma unroll
        for (int j = 0; j < 4; j++) {
            float2 f = __half22float2(*(const __half2*)&u[j]);
            mn = fminf(mn, fminf(f.x, f.y));
        }
    }
    #pragma unroll
    for (int o = 16; o > 0; o >>= 1) mn = fminf(mn, __shfl_xor_sync(0xFFFFFFFFu, mn, o));
    if (lane == 0) rs[wid] = mn;
    __syncthreads();
    if (t == 0) {
        float l1z = 0.0f, m = 3.4e38f;
        #pragma unroll
        for (int i = 0; i < 8; i++) { l1z += rl[i]; m = fminf(m, rs[i]); }
        float sz = g_sz[row];
        float scm = __uint_as_float(g_scmax_bits);
        float l1cm = __uint_as_float(g_l1cmax_bits);
        // sound margin: 2*(quantization error bound) + fp16 store rounding slack
        thrS = m + 2.0f * (sz * l1cm + scm * l1z + 768.0f * sz * scm) + 10.0f;
    }
    __syncthreads();

    const float thr = thrS;
    #pragma unroll
    for (int i = 0; i < 4; i++) {
        const unsigned* u = (const unsigned*)&sv[i];
        #pragma unroll
        for (int j = 0; j < 4; j++) {
            float2 f = __half22float2(*(const __half2*)&u[j]);
            if (f.x <= thr) {
                int p = atomicAdd(&cnt, 1);
                if (p < MAXCAND) list[p] = (t + (i << 8)) * 8 + j * 2;
            }
            if (f.y <= thr) {
                int p = atomicAdd(&cnt, 1);
                if (p < MAXCAND) list[p] = (t + (i << 8)) * 8 + j * 2 + 1;
            }
        }
    }
    __syncthreads();

    if (cnt <= MAXCAND) {
        const int n = cnt;
        for (int j = wid; j < n; j += 8) {
            const int k = list[j];
            const float4* crow = (const float4*)(cb + (size_t)k * Dn);
            const float4* zrow = (const float4*)zs;
            float d = 0.0f;
            #pragma unroll
            for (int c = lane; c < Dn / 4; c += 32) {
                float4 aa = zrow[c], bb = crow[c];
                d += aa.x * bb.x + aa.y * bb.y + aa.z * bb.z + aa.w * bb.w;
            }
            #pragma unroll
            for (int o = 16; o > 0; o >>= 1) d += __shfl_xor_sync(0xFFFFFFFFu, d, o);
            if (lane == 0) {
                float ex = fmaf(-2.0f, d, g_csq[k]);
                unsigned long long pk =
                    ((unsigned long long)f2ord(ex) << 32) | (unsigned)k;
                atomicMin(&bestPk, pk);
            }
        }
    } else {
        for (int k = t; k < Kn; k += 256) {
            const float* crow = cb + (size_t)k * Dn;
            float d = 0.0f;
            for (int c = 0; c < Dn; c++) d += zs[c] * crow[c];
            float ex = fmaf(-2.0f, d, g_csq[k]);
            unsigned long long pk =
                ((unsigned long long)f2ord(ex) << 32) | (unsigned)k;
            atomicMin(&bestPk, pk);
        }
    }
    __syncthreads();

    const int idx = (int)(unsigned)(bestPk & 0xFFFFFFFFull);
    float2 cq = ((const float2*)(cb + (size_t)idx * Dn))[t];
    ((float2*)(out + (size_t)row * Dn))[t] = cq;       // z_q
    float* es = g_embed + (size_t)idx * Dn + t * 2;
    atomicAdd(es + 0, zv.x);
    atomicAdd(es + 1, zv.y);
    if (t == 0) {
        atomicAdd(&g_counts[idx], 1.0f);
        out[(size_t)Bn * Dn + row] = (float)idx;       // indices
    }
}

// ---------------------------------------------------------------------------
__global__ void ema_kernel(const float* __restrict__ ema_cs,
                           const float* __restrict__ ema_cb,
                           float* __restrict__ out) {
    const int k = blockIdx.x;
    const int t = threadIdx.x;

    const size_t offCb  = (size_t)Bn * Dn + Bn;
    const size_t offCs  = offCb + (size_t)Kn * Dn;
    const size_t offEma = offCs + Kn;

    float ncs = DECAYF * ema_cs[k] + OMDF * g_counts[k];
    float inv = 1.0f / (ncs + EPSF);
    if (t == 0) out[offCs + k] = ncs;

    float4 ev = ((const float4*)(ema_cb + (size_t)k * Dn))[t];
    float4 sv = ((const float4*)(g_embed + (size_t)k * Dn))[t];
    float4 ne;
    ne.x = DECAYF * ev.x + OMDF * sv.x;
    ne.y = DECAYF * ev.y + OMDF * sv.y;
    ne.z = DECAYF * ev.z + OMDF * sv.z;
    ne.w = DECAYF * ev.w + OMDF * sv.w;
    ((float4*)(out + offEma + (size_t)k * Dn))[t] = ne;
    float4 nc;
    nc.x = ne.x * inv; nc.y = ne.y * inv; nc.z = ne.z * inv; nc.w = ne.w * inv;
    ((float4*)(out + offCb + (size_t)k * Dn))[t] = nc;
}

// ---------------------------------------------------------------------------
extern "C" void kernel_launch(void* const* d_in, const int* in_sizes, int n_in,
                              void* d_out, int out_size) {
    const float* z_e    = (const float*)d_in[0];
    const float* cb     = (const float*)d_in[1];
    const float* ema_cs = (const float*)d_in[2];
    const float* ema_cb = (const float*)d_in[3];
    float* out = (float*)d_out;

    cudaFuncSetAttribute(gemm_kernel,
                         cudaFuncAttributeMaxDynamicSharedMemorySize, SMEM_BYTES);

    zero_kernel<<<4096, 256>>>();
    quantA_kernel<<<Bn / 8, 256>>>(z_e);
    quantB_kernel<<<Kn / 8, 256>>>(cb);
    gemm_kernel<<<(Bn / 128) * (Kn / 128), 128, SMEM_BYTES>>>();
    select_kernel<<<Bn, 256>>>(z_e, cb, out);
    ema_kernel<<<Kn, 128>>>(ema_cs, ema_cb, out);
}

// round 12
// speedup vs baseline: 8.2094x; 8.2094x over previous
#include <cuda_runtime.h>
#include <cuda_fp16.h>
#include <cstdint>

#define Bn 32768
#define Kn 8192
#define Dn 512
#define DECAYF 0.99f
#define OMDF   0.01f
#define EPSF   1e-5f

#define NITER 8              // K=512, BLK_K=64
#define STB 18432            // bytes per stage: 128 rows * 144B
#define SM_CSQ  110592       // after 3*STB*2
#define SMEM_BYTES 111104

// Device scratch (allocation-free). NEVER referenced from host code.
__device__ uint4  g_A4[(size_t)Bn * Dn * 2 / 16];     // fp16 of z_e
__device__ uint4  g_B4[(size_t)Kn * Dn * 2 / 16];     // fp16 of codebook
__device__ __half g_scores[(size_t)Bn * Kn];          // approx scores
__device__ float  g_embed[(size_t)Kn * Dn];
__device__ float  g_counts[Kn];
__device__ float  g_csq[Kn];
__device__ unsigned g_cmax_bits;                      // max csq (float bits)

__device__ __forceinline__ uint32_t smem_u32(const void* p) {
    uint32_t a;
    asm("{ .reg .u64 t; cvta.to.shared.u64 t, %1; cvt.u32.u64 %0, t; }"
        : "=r"(a) : "l"(p));
    return a;
}
__device__ __forceinline__ void cpa16(uint32_t s, const void* g) {
    asm volatile("cp.async.cg.shared.global [%0], [%1], 16;" :: "r"(s), "l"(g));
}
#define CP_COMMIT() asm volatile("cp.async.commit_group;" ::: "memory")
#define CP_WAIT1()  asm volatile("cp.async.wait_group 1;" ::: "memory")

__device__ __forceinline__ void ldsm4(uint32_t& r0, uint32_t& r1, uint32_t& r2,
                                      uint32_t& r3, uint32_t addr) {
    asm volatile("ldmatrix.sync.aligned.m8n8.x4.shared.b16 {%0,%1,%2,%3}, [%4];"
                 : "=r"(r0), "=r"(r1), "=r"(r2), "=r"(r3) : "r"(addr));
}
// fp16-accumulator HMMA: D,C are 2x b32 (4 halves)
__device__ __forceinline__ void hmma16(uint32_t* c, uint32_t a0, uint32_t a1,
                                       uint32_t a2, uint32_t a3,
                                       uint32_t b0, uint32_t b1) {
    asm volatile(
        "mma.sync.aligned.m16n8k16.row.col.f16.f16.f16.f16 "
        "{%0,%1}, {%2,%3,%4,%5}, {%6,%7}, {%0,%1};"
        : "+r"(c[0]), "+r"(c[1])
        : "r"(a0), "r"(a1), "r"(a2), "r"(a3), "r"(b0), "r"(b1));
}
__device__ __forceinline__ unsigned f2ord(float f) {
    unsigned u = __float_as_uint(f);
    return (u & 0x80000000u) ? ~u : (u | 0x80000000u);
}

// ---------------------------------------------------------------------------
__global__ void zero_kernel() {
    int stride = gridDim.x * blockDim.x;
    int t = blockIdx.x * blockDim.x + threadIdx.x;
    const int N = Kn * Dn;
    for (int i = t; i < N; i += stride) g_embed[i] = 0.0f;
    if (t < Kn) g_counts[t] = 0.0f;
    if (t == 0) g_cmax_bits = 0u;
}

// z_e fp32 -> fp16, vectorized 4-wide
__global__ void splitA_kernel(const float* __restrict__ src) {
    ushort4* dst = (ushort4*)(void*)g_A4;
    int stride = gridDim.x * blockDim.x;
    const int n4 = Bn * Dn / 4;
    for (int i = blockIdx.x * blockDim.x + threadIdx.x; i < n4; i += stride) {
        float4 v = ((const float4*)src)[i];
        __half2 lo = __floats2half2_rn(v.x, v.y);
        __half2 hi = __floats2half2_rn(v.z, v.w);
        ushort4 o;
        o.x = *(unsigned short*)&lo;  o.y = ((unsigned short*)&lo)[1];
        o.z = *(unsigned short*)&hi;  o.w = ((unsigned short*)&hi)[1];
        dst[i] = o;
    }
}

// codebook fp32 -> fp16 AND csq, one warp per row
__global__ void splitB_csq_kernel(const float* __restrict__ cb) {
    int warp = (blockIdx.x * blockDim.x + threadIdx.x) >> 5;
    int lane = threadIdx.x & 31;
    if (warp >= Kn) return;
    const float4* row = (const float4*)(cb + (size_t)warp * Dn);
    ushort4* drow = (ushort4*)((__half*)(void*)g_B4 + (size_t)warp * Dn);
    float s = 0.0f;
    #pragma unroll
    for (int i = lane; i < Dn / 4; i += 32) {
        float4 v = row[i];
        s += v.x * v.x + v.y * v.y + v.z * v.z + v.w * v.w;
        __half2 lo = __floats2half2_rn(v.x, v.y);
        __half2 hi = __floats2half2_rn(v.z, v.w);
        ushort4 o;
        o.x = *(unsigned short*)&lo;  o.y = ((unsigned short*)&lo)[1];
        o.z = *(unsigned short*)&hi;  o.w = ((unsigned short*)&hi)[1];
        drow[i] = o;
    }
    #pragma unroll
    for (int o = 16; o > 0; o >>= 1) s += __shfl_xor_sync(0xFFFFFFFFu, s, o);
    if (lane == 0) {
        g_csq[warp] = s;
        atomicMax(&g_cmax_bits, __float_as_uint(s));
    }
}

// ---------------------------------------------------------------------------
// Pass 1: fp16 GEMM (fp16 accumulate), scores streamed to g_scores as fp16.
// Block 128x128, 8 warps (4x2), warp tile 32x64, BLK_K=64, 3-slot cp.async.
// ---------------------------------------------------------------------------
__global__ void __launch_bounds__(256, 2)
gemm_kernel() {
    extern __shared__ char sm[];
    const uint32_t sA = smem_u32(sm);
    const uint32_t sB = sA + 3 * STB;
    float* csq_s = (float*)(sm + SM_CSQ);

    const int tid = threadIdx.x;
    const int lane = tid & 31;
    const int w = tid >> 5;
    const int warpM = w & 3;
    const int warpN = w >> 2;
    const int rowBase = (blockIdx.x >> 6) * 128;
    const int colBase = (blockIdx.x & 63) * 128;   // colTile-fastest: B L2-resident

    if (tid < 128) csq_s[tid] = g_csq[colBase + tid];

    const __half* A = (const __half*)(void*)g_A4;
    const __half* Bm = (const __half*)(void*)g_B4;

    const int lr = tid >> 3, lc = tid & 7;
    const uint32_t soBase = (uint32_t)(lr * 144 + lc * 16);
    const __half* gA = A + (size_t)(rowBase + lr) * Dn + lc * 8;
    const __half* gB = Bm + (size_t)(colBase + lr) * Dn + lc * 8;

    uint32_t acc[2][8][2];                 // fp16x2 accumulators
    #pragma unroll
    for (int mt = 0; mt < 2; mt++)
        #pragma unroll
        for (int nt = 0; nt < 8; nt++) { acc[mt][nt][0] = 0u; acc[mt][nt][1] = 0u; }

    const int lrow = lane & 15;
    const int khalf = lane >> 4;
    const uint32_t aRowOff = (uint32_t)((warpM * 32 + lrow) * 144 + khalf * 16);
    const uint32_t bRowOff = (uint32_t)((warpN * 64 + lrow) * 144 + khalf * 16);

    #define LOAD_STAGE(s, slot) do {                                           \
        int _off = (s) << 6;                                                   \
        uint32_t _da = sA + (slot) * STB;                                      \
        uint32_t _db = sB + (slot) * STB;                                      \
        _Pragma("unroll")                                                      \
        for (int it = 0; it < 4; it++) {                                       \
            uint32_t so = soBase + it * 32 * 144;                              \
            cpa16(_da + so, gA + (size_t)(it * 32) * Dn + _off);               \
            cpa16(_db + so, gB + (size_t)(it * 32) * Dn + _off);               \
        }                                                                      \
    } while (0)

    LOAD_STAGE(0, 0); CP_COMMIT();
    LOAD_STAGE(1, 1); CP_COMMIT();

    int slot = 0, nslot = 2;
    #pragma unroll 1
    for (int s = 0; s < NITER; s++) {
        CP_WAIT1();
        __syncthreads();
        if (s + 2 < NITER) LOAD_STAGE(s + 2, nslot);
        CP_COMMIT();

        const uint32_t da = sA + slot * STB;
        const uint32_t db = sB + slot * STB;
        #pragma unroll
        for (int k16 = 0; k16 < 4; k16++) {
            uint32_t a[2][4];
            #pragma unroll
            for (int mt = 0; mt < 2; mt++)
                ldsm4(a[mt][0], a[mt][1], a[mt][2], a[mt][3],
                      da + aRowOff + mt * 16 * 144 + k16 * 32);
            uint32_t b[4][4];
            #pragma unroll
            for (int np = 0; np < 4; np++)
                ldsm4(b[np][0], b[np][1], b[np][2], b[np][3],
                      db + bRowOff + np * 16 * 144 + k16 * 32);
            #pragma unroll
            for (int mt = 0; mt < 2; mt++)
                #pragma unroll
                for (int nt = 0; nt < 8; nt++)
                    hmma16(acc[mt][nt],
                           a[mt][0], a[mt][1], a[mt][2], a[mt][3],
                           b[nt >> 1][(nt & 1) ? 1 : 0],
                           b[nt >> 1][(nt & 1) ? 3 : 2]);
        }
        slot = slot == 2 ? 0 : slot + 1;
        nslot = nslot == 2 ? 0 : nslot + 1;
    }
    #undef LOAD_STAGE

    // epilogue: score = csq - 2*dot, streamed fp16 writes.
    // f16-acc D frag: reg[half] = rows (g + half*8), cols (2tg, 2tg+1)
    const int g = lane >> 2, tg = lane & 3;
    #pragma unroll
    for (int mt = 0; mt < 2; mt++) {
        #pragma unroll
        for (int half = 0; half < 2; half++) {
            int grow = rowBase + warpM * 32 + mt * 16 + half * 8 + g;
            unsigned* dst = (unsigned*)(g_scores + (size_t)grow * Kn + colBase);
            #pragma unroll
            for (int nt = 0; nt < 8; nt++) {
                int cl = warpN * 64 + nt * 8 + tg * 2;
                float2 f = __half22float2(*(const __half2*)&acc[mt][nt][half]);
                float s0 = fmaf(-2.0f, f.x, csq_s[cl]);
                float s1 = fmaf(-2.0f, f.y, csq_s[cl + 1]);
                __half2 h = __floats2half2_rn(s0, s1);
                __stcs(dst + (cl >> 1), *(unsigned*)&h);
            }
        }
    }
}

// ---------------------------------------------------------------------------
// Pass 2 (fused with scatter): scan scores, exact fp32 rescore of candidates,
// write z_q + indices, atomic scatter counts/embed. One 256-thread block/row.
// ---------------------------------------------------------------------------
#define MAXCAND 128
__global__ void __launch_bounds__(256)
select_kernel(const float* __restrict__ z_e, const float* __restrict__ cb,
              float* __restrict__ out) {
    __shared__ float zs[Dn];
    __shared__ float rz[8], rs[8];
    __shared__ int list[MAXCAND];
    __shared__ int cnt;
    __shared__ float thrS;
    __shared__ unsigned long long bestPk;

    const int row = blockIdx.x;
    const int t = threadIdx.x;
    const int lane = t & 31, wid = t >> 5;

    float2 zv = ((const float2*)(z_e + (size_t)row * Dn))[t];
    ((float2*)zs)[t] = zv;
    float zp = zv.x * zv.x + zv.y * zv.y;
    #pragma unroll
    for (int o = 16; o > 0; o >>= 1) zp += __shfl_xor_sync(0xFFFFFFFFu, zp, o);
    if (lane == 0) rz[wid] = zp;
    if (t == 0) { cnt = 0; bestPk = 0xFFFFFFFFFFFFFFFFull; }

    const uint4* sr = (const uint4*)(g_scores + (size_t)row * Kn);
    uint4 sv[4];
    float mn = 3.4e38f;
    #pragma unroll
    for (int i = 0; i < 4; i++) {
        sv[i] = __ldcs(sr + t + (i << 8));
        const unsigned* u = (const unsigned*)&sv[i];
        #pragma unroll
        for (int j = 0; j < 4; j++) {
            float2 f = __half22float2(*(const __half2*)&u[j]);
            mn = fminf(mn, fminf(f.x, f.y));
        }
    }
    #pragma unroll
    for (int o = 16; o > 0; o >>= 1) mn = fminf(mn, __shfl_xor_sync(0xFFFFFFFFu, mn, o));
    if (lane == 0) rs[wid] = mn;
    __syncthreads();
    if (t == 0) {
        float zsq = 0.0f, m = 3.4e38f;
        #pragma unroll
        for (int i = 0; i < 8; i++) { zsq += rz[i]; m = fminf(m, rs[i]); }
        float cmax = __uint_as_float(g_cmax_bits);
        // sound margin: h0-rounding bound + fp16-accumulation bound + slack
        thrS = m + 0.001953125f * sqrtf(zsq * cmax) + 16.0f;
    }
    __syncthreads();

    const float thr = thrS;
    #pragma unroll
    for (int i = 0; i < 4; i++) {
        const unsigned* u = (const unsigned*)&sv[i];
        #pragma unroll
        for (int j = 0; j < 4; j++) {
            float2 f = __half22float2(*(const __half2*)&u[j]);
            if (f.x <= thr) {
                int p = atomicAdd(&cnt, 1);
                if (p < MAXCAND) list[p] = (t + (i << 8)) * 8 + j * 2;
            }
            if (f.y <= thr) {
                int p = atomicAdd(&cnt, 1);
                if (p < MAXCAND) list[p] = (t + (i << 8)) * 8 + j * 2 + 1;
            }
        }
    }
    __syncthreads();

    if (cnt <= MAXCAND) {
        const int n = cnt;
        for (int j = wid; j < n; j += 8) {
            const int k = list[j];
            const float4* crow = (const float4*)(cb + (size_t)k * Dn);
            const float4* zrow = (const float4*)zs;
            float d = 0.0f;
            #pragma unroll
            for (int c = lane; c < Dn / 4; c += 32) {
                float4 aa = zrow[c], bb = crow[c];
                d += aa.x * bb.x + aa.y * bb.y + aa.z * bb.z + aa.w * bb.w;
            }
            #pragma unroll
            for (int o = 16; o > 0; o >>= 1) d += __shfl_xor_sync(0xFFFFFFFFu, d, o);
            if (lane == 0) {
                float ex = fmaf(-2.0f, d, g_csq[k]);
                unsigned long long pk =
                    ((unsigned long long)f2ord(ex) << 32) | (unsigned)k;
                atomicMin(&bestPk, pk);
            }
        }
    } else {
        for (int k = t; k < Kn; k += 256) {
            const float* crow = cb + (size_t)k * Dn;
            float d = 0.0f;
            for (int c = 0; c < Dn; c++) d += zs[c] * crow[c];
            float ex = fmaf(-2.0f, d, g_csq[k]);
            unsigned long long pk =
                ((unsigned long long)f2ord(ex) << 32) | (unsigned)k;
            atomicMin(&bestPk, pk);
        }
    }
    __syncthreads();

    const int idx = (int)(unsigned)(bestPk & 0xFFFFFFFFull);
    float2 cq = ((const float2*)(cb + (size_t)idx * Dn))[t];
    ((float2*)(out + (size_t)row * Dn))[t] = cq;       // z_q
    float* es = g_embed + (size_t)idx * Dn + t * 2;
    atomicAdd(es + 0, zv.x);
    atomicAdd(es + 1, zv.y);
    if (t == 0) {
        atomicAdd(&g_counts[idx], 1.0f);
        out[(size_t)Bn * Dn + row] = (float)idx;       // indices
    }
}

// ---------------------------------------------------------------------------
__global__ void ema_kernel(const float* __restrict__ ema_cs,
                           const float* __restrict__ ema_cb,
                           float* __restrict__ out) {
    const int k = blockIdx.x;
    const int t = threadIdx.x;

    const size_t offCb  = (size_t)Bn * Dn + Bn;
    const size_t offCs  = offCb + (size_t)Kn * Dn;
    const size_t offEma = offCs + Kn;

    float ncs = DECAYF * ema_cs[k] + OMDF * g_counts[k];
    float inv = 1.0f / (ncs + EPSF);
    if (t == 0) out[offCs + k] = ncs;

    float4 ev = ((const float4*)(ema_cb + (size_t)k * Dn))[t];
    float4 sv = ((const float4*)(g_embed + (size_t)k * Dn))[t];
    float4 ne;
    ne.x = DECAYF * ev.x + OMDF * sv.x;
    ne.y = DECAYF * ev.y + OMDF * sv.y;
    ne.z = DECAYF * ev.z + OMDF * sv.z;
    ne.w = DECAYF * ev.w + OMDF * sv.w;
    ((float4*)(out + offEma + (size_t)k * Dn))[t] = ne;
    float4 nc;
    nc.x = ne.x * inv; nc.y = ne.y * inv; nc.z = ne.z * inv; nc.w = ne.w * inv;
    ((float4*)(out + offCb + (size_t)k * Dn))[t] = nc;
}

// ---------------------------------------------------------------------------
extern "C" void kernel_launch(void* const* d_in, const int* in_sizes, int n_in,
                              void* d_out, int out_size) {
    const float* z_e    = (const float*)d_in[0];
    const float* cb     = (const float*)d_in[1];
    const float* ema_cs = (const float*)d_in[2];
    const float* ema_cb = (const float*)d_in[3];
    float* out = (float*)d_out;

    cudaFuncSetAttribute(gemm_kernel,
                         cudaFuncAttributeMaxDynamicSharedMemorySize, SMEM_BYTES);

    zero_kernel<<<4096, 256>>>();
    splitA_kernel<<<4096, 256>>>(z_e);
    splitB_csq_kernel<<<Kn / 8, 256>>>(cb);
    gemm_kernel<<<(Bn / 128) * (Kn / 128), 256, SMEM_BYTES>>>();
    select_kernel<<<Bn, 256>>>(z_e, cb, out);
    ema_kernel<<<Kn, 128>>>(ema_cs, ema_cb, out);
}